// round 1
// baseline (speedup 1.0000x reference)
#include <cuda_runtime.h>
#include <math.h>

#define BATCH 4
#define SEQ   4096
#define DIM   1024
#define NH    4
#define DH    256
#define FFD   4096
#define TOK   (BATCH*SEQ)   /* 16384 */
#define NBH   (BATCH*NH)    /* 16 */
#define KCH   16            /* k-softmax seq chunks */
#define CHUNK (SEQ/KCH)     /* 256 */

// ---------------- scratch (device globals; no allocation allowed) ----------
__device__ float g_h   [(size_t)TOK*DIM];
__device__ float g_q   [(size_t)NBH*SEQ*DH];
__device__ float g_k   [(size_t)NBH*SEQ*DH];
__device__ float g_v   [(size_t)NBH*SEQ*DH];
__device__ float g_ctx [(size_t)NBH*DH*DH];
__device__ float g_attn[(size_t)TOK*DIM];
__device__ float g_x1  [(size_t)TOK*DIM];
__device__ float g_x2  [(size_t)TOK*DIM];
__device__ float g_ff  [(size_t)TOK*FFD];
__device__ float g_part[NBH*KCH*2*DH];

__device__ __forceinline__ float gelu_tanh(float x) {
    float x3 = x*x*x;
    return 0.5f*x*(1.0f + tanhf(0.7978845608028654f*(x + 0.044715f*x3)));
}

// ---------------- LayerNorm: one block per row of 1024 ---------------------
__global__ void ln_kernel(const float* __restrict__ x, const float* __restrict__ g,
                          const float* __restrict__ b, float* __restrict__ out)
{
    __shared__ float red[16];
    __shared__ float s_mu, s_rstd;
    const int row = blockIdx.x, t = threadIdx.x;
    const float4 v = ((const float4*)(x + (size_t)row*DIM))[t];
    float s  = v.x + v.y + v.z + v.w;
    float ss = fmaf(v.x,v.x, fmaf(v.y,v.y, fmaf(v.z,v.z, v.w*v.w)));
    #pragma unroll
    for (int o = 16; o > 0; o >>= 1) {
        s  += __shfl_xor_sync(0xffffffffu, s,  o);
        ss += __shfl_xor_sync(0xffffffffu, ss, o);
    }
    const int w = t >> 5, lane = t & 31;
    if (lane == 0) { red[w] = s; red[8+w] = ss; }
    __syncthreads();
    if (t == 0) {
        float S = 0.f, SS = 0.f;
        #pragma unroll
        for (int i = 0; i < 8; i++) { S += red[i]; SS += red[8+i]; }
        float mu  = S  * (1.0f/DIM);
        float var = SS * (1.0f/DIM) - mu*mu;
        s_mu = mu; s_rstd = rsqrtf(var + 1e-5f);
    }
    __syncthreads();
    const float mu = s_mu, r = s_rstd;
    const float4 gv = ((const float4*)g)[t];
    const float4 bv = ((const float4*)b)[t];
    float4 o;
    o.x = (v.x-mu)*r*gv.x + bv.x;
    o.y = (v.y-mu)*r*gv.y + bv.y;
    o.z = (v.z-mu)*r*gv.z + bv.z;
    o.w = (v.w-mu)*r*gv.w + bv.w;
    ((float4*)(out + (size_t)row*DIM))[t] = o;
}

// ---------------- generic 128x128x8 SGEMM, fused epilogues -----------------
// MODE 0: C = acc + bias
// MODE 1: C = acc + bias + res
// MODE 2: C = gelu(acc + bias)
// MODE 3: C = acc, scattered to [b,h,n,dh] head-split layout (no bias)
template<int MODE>
__global__ void __launch_bounds__(256)
gemm_main(const float* __restrict__ A, const float* __restrict__ W,
          const float* __restrict__ bias, const float* __restrict__ res,
          float* __restrict__ C, int M, int Ncols, int K)
{
    __shared__ float As[8][128];
    __shared__ float Bs[8][128];
    const int tid = threadIdx.x;
    const int tx = tid & 15, ty = tid >> 4;
    const int row0 = blockIdx.y * 128;
    const int col0 = blockIdx.x * 128;
    const int a_row = tid >> 1, a_col = (tid & 1) * 4;
    const int b_row = tid >> 5, b_col = (tid & 31) * 4;

    const float* Ap = A + (size_t)(row0 + a_row) * K + a_col;
    const float* Wp = W + (size_t)b_row * Ncols + col0 + b_col;

    float acc[8][8] = {};

    for (int k0 = 0; k0 < K; k0 += 8) {
        float4 av = *(const float4*)Ap;
        float4 bv = *(const float4*)Wp;
        As[a_col+0][a_row] = av.x;
        As[a_col+1][a_row] = av.y;
        As[a_col+2][a_row] = av.z;
        As[a_col+3][a_row] = av.w;
        *(float4*)&Bs[b_row][b_col] = bv;
        __syncthreads();
        #pragma unroll
        for (int kk = 0; kk < 8; kk++) {
            float4 a0 = *(const float4*)&As[kk][ty*8];
            float4 a1 = *(const float4*)&As[kk][ty*8+4];
            float4 b0 = *(const float4*)&Bs[kk][tx*8];
            float4 b1 = *(const float4*)&Bs[kk][tx*8+4];
            float ar[8] = {a0.x,a0.y,a0.z,a0.w,a1.x,a1.y,a1.z,a1.w};
            float br[8] = {b0.x,b0.y,b0.z,b0.w,b1.x,b1.y,b1.z,b1.w};
            #pragma unroll
            for (int i = 0; i < 8; i++)
                #pragma unroll
                for (int j = 0; j < 8; j++)
                    acc[i][j] = fmaf(ar[i], br[j], acc[i][j]);
        }
        __syncthreads();
        Ap += 8;
        Wp += (size_t)8 * Ncols;
    }

    const int r0 = row0 + ty*8;
    const int c0 = col0 + tx*8;

    if (MODE == 3) {
        const int head = c0 >> 8;      // DH = 256; 8-wide stores never cross head
        const int dh0  = c0 & 255;
        #pragma unroll
        for (int i = 0; i < 8; i++) {
            const int r = r0 + i;
            const int b = r >> 12;     // SEQ = 4096
            const int n = r & 4095;
            float* op = C + ((size_t)((b*NH + head)*SEQ + n))*DH + dh0;
            *(float4*)(op)   = make_float4(acc[i][0], acc[i][1], acc[i][2], acc[i][3]);
            *(float4*)(op+4) = make_float4(acc[i][4], acc[i][5], acc[i][6], acc[i][7]);
        }
    } else {
        const float4 bi0 = *(const float4*)(bias + c0);
        const float4 bi1 = *(const float4*)(bias + c0 + 4);
        const float bb[8] = {bi0.x,bi0.y,bi0.z,bi0.w,bi1.x,bi1.y,bi1.z,bi1.w};
        #pragma unroll
        for (int i = 0; i < 8; i++) {
            const int r = r0 + i;
            float vout[8];
            #pragma unroll
            for (int j = 0; j < 8; j++) {
                float val = acc[i][j] + bb[j];
                if (MODE == 2) val = gelu_tanh(val);
                vout[j] = val;
            }
            if (MODE == 1) {
                const float* rp = res + (size_t)r*Ncols + c0;
                const float4 rv0 = *(const float4*)rp;
                const float4 rv1 = *(const float4*)(rp+4);
                vout[0]+=rv0.x; vout[1]+=rv0.y; vout[2]+=rv0.z; vout[3]+=rv0.w;
                vout[4]+=rv1.x; vout[5]+=rv1.y; vout[6]+=rv1.z; vout[7]+=rv1.w;
            }
            float* op = C + (size_t)r*Ncols + c0;
            *(float4*)(op)   = make_float4(vout[0],vout[1],vout[2],vout[3]);
            *(float4*)(op+4) = make_float4(vout[4],vout[5],vout[6],vout[7]);
        }
    }
}

// ---------------- q softmax over head dim (256), one warp per row ----------
__global__ void qsm_kernel(float* __restrict__ q)
{
    const int warp = (blockIdx.x * blockDim.x + threadIdx.x) >> 5;
    const int lane = threadIdx.x & 31;
    float* row = q + (size_t)warp * DH;
    float v[8];
    float m = -INFINITY;
    #pragma unroll
    for (int j = 0; j < 8; j++) { v[j] = row[j*32 + lane] * 0.25f; m = fmaxf(m, v[j]); }
    #pragma unroll
    for (int o = 16; o > 0; o >>= 1) m = fmaxf(m, __shfl_xor_sync(0xffffffffu, m, o));
    float s = 0.f;
    #pragma unroll
    for (int j = 0; j < 8; j++) { v[j] = expf(v[j] - m); s += v[j]; }
    #pragma unroll
    for (int o = 16; o > 0; o >>= 1) s += __shfl_xor_sync(0xffffffffu, s, o);
    const float inv = 1.0f / s;
    #pragma unroll
    for (int j = 0; j < 8; j++) row[j*32 + lane] = v[j] * inv;
}

// ---------------- k softmax over sequence dim (4096), chunked 2-pass -------
__global__ void ksm_partial(const float* __restrict__ k, float* __restrict__ part)
{
    const int bh = blockIdx.y, ch = blockIdx.x, t = threadIdx.x;
    const float* kp = k + ((size_t)bh*SEQ + (size_t)ch*CHUNK)*DH + t;
    float m = -INFINITY, s = 0.f;
    for (int i = 0; i < CHUNK; i++) {
        const float vv = kp[(size_t)i*DH] * 0.25f;
        const float nm = fmaxf(m, vv);
        s = s*expf(m - nm) + expf(vv - nm);
        m = nm;
    }
    float* pp = part + (size_t)((bh*KCH + ch)*2)*DH;
    pp[t] = m; pp[DH + t] = s;
}

__global__ void ksm_norm(float* __restrict__ k, const float* __restrict__ part)
{
    const int bh = blockIdx.y, ch = blockIdx.x, t = threadIdx.x;
    float M = -INFINITY;
    #pragma unroll
    for (int c = 0; c < KCH; c++)
        M = fmaxf(M, part[(size_t)((bh*KCH + c)*2)*DH + t]);
    float S = 0.f;
    #pragma unroll
    for (int c = 0; c < KCH; c++) {
        const float* pp = part + (size_t)((bh*KCH + c)*2)*DH;
        S += pp[DH + t] * expf(pp[t] - M);
    }
    const float inv = 1.0f / S;
    float* kp = k + ((size_t)bh*SEQ + (size_t)ch*CHUNK)*DH + t;
    for (int i = 0; i < CHUNK; i++) {
        const float vv = kp[(size_t)i*DH] * 0.25f;
        kp[(size_t)i*DH] = expf(vv - M) * inv;
    }
}

// ---------------- context: ctx[bh] = k[bh]^T @ v[bh]   (256x4096 ^T x 4096x256)
__global__ void __launch_bounds__(256)
ctx_gemm(const float* __restrict__ k, const float* __restrict__ v, float* __restrict__ ctx)
{
    __shared__ float As[16][64];
    __shared__ float Bs[16][64];
    const int bh = blockIdx.z;
    const int m0 = blockIdx.y * 64, e0 = blockIdx.x * 64;
    const int tid = threadIdx.x;
    const int tx = tid & 15, ty = tid >> 4;
    const int lr = tid >> 4;          // 0..15 (seq row within tile)
    const int lc = (tid & 15) * 4;    // 0..60
    const float* kb = k + (size_t)bh*SEQ*DH;
    const float* vb = v + (size_t)bh*SEQ*DH;
    float acc[4][4] = {};

    for (int n0 = 0; n0 < SEQ; n0 += 16) {
        *(float4*)&As[lr][lc] = *(const float4*)(kb + (size_t)(n0+lr)*DH + m0 + lc);
        *(float4*)&Bs[lr][lc] = *(const float4*)(vb + (size_t)(n0+lr)*DH + e0 + lc);
        __syncthreads();
        #pragma unroll
        for (int kk = 0; kk < 16; kk++) {
            float4 a = *(const float4*)&As[kk][ty*4];
            float4 b = *(const float4*)&Bs[kk][tx*4];
            const float ar[4] = {a.x,a.y,a.z,a.w};
            const float br[4] = {b.x,b.y,b.z,b.w};
            #pragma unroll
            for (int i = 0; i < 4; i++)
                #pragma unroll
                for (int j = 0; j < 4; j++)
                    acc[i][j] = fmaf(ar[i], br[j], acc[i][j]);
        }
        __syncthreads();
    }
    float* cb = ctx + (size_t)bh*DH*DH;
    #pragma unroll
    for (int i = 0; i < 4; i++)
        *(float4*)(cb + (size_t)(m0 + ty*4 + i)*DH + e0 + tx*4) =
            make_float4(acc[i][0], acc[i][1], acc[i][2], acc[i][3]);
}

// ---------------- attn out: q[bh] @ ctx[bh], scatter to [b,n,d] ------------
__global__ void __launch_bounds__(256)
attn_gemm(const float* __restrict__ q, const float* __restrict__ ctx, float* __restrict__ attn)
{
    __shared__ float As[8][128];
    __shared__ float Bs[8][128];
    const int bh = blockIdx.z;
    const int b = bh >> 2, head = bh & 3;
    const float* A = q   + (size_t)bh*SEQ*DH;
    const float* W = ctx + (size_t)bh*DH*DH;
    const int tid = threadIdx.x;
    const int tx = tid & 15, ty = tid >> 4;
    const int row0 = blockIdx.y * 128, col0 = blockIdx.x * 128;
    const int a_row = tid >> 1, a_col = (tid & 1) * 4;
    const int b_row = tid >> 5, b_col = (tid & 31) * 4;
    const float* Ap = A + (size_t)(row0 + a_row)*DH + a_col;
    const float* Wp = W + (size_t)b_row*DH + col0 + b_col;
    float acc[8][8] = {};

    for (int k0 = 0; k0 < DH; k0 += 8) {
        float4 av = *(const float4*)Ap;
        float4 bv = *(const float4*)Wp;
        As[a_col+0][a_row] = av.x;
        As[a_col+1][a_row] = av.y;
        As[a_col+2][a_row] = av.z;
        As[a_col+3][a_row] = av.w;
        *(float4*)&Bs[b_row][b_col] = bv;
        __syncthreads();
        #pragma unroll
        for (int kk = 0; kk < 8; kk++) {
            float4 a0 = *(const float4*)&As[kk][ty*8];
            float4 a1 = *(const float4*)&As[kk][ty*8+4];
            float4 b0 = *(const float4*)&Bs[kk][tx*8];
            float4 b1 = *(const float4*)&Bs[kk][tx*8+4];
            float ar[8] = {a0.x,a0.y,a0.z,a0.w,a1.x,a1.y,a1.z,a1.w};
            float br[8] = {b0.x,b0.y,b0.z,b0.w,b1.x,b1.y,b1.z,b1.w};
            #pragma unroll
            for (int i = 0; i < 8; i++)
                #pragma unroll
                for (int j = 0; j < 8; j++)
                    acc[i][j] = fmaf(ar[i], br[j], acc[i][j]);
        }
        __syncthreads();
        Ap += 8;
        Wp += 8*DH;
    }

    const int r0 = row0 + ty*8;   // n within bh
    const int c0 = col0 + tx*8;   // e
    #pragma unroll
    for (int i = 0; i < 8; i++) {
        const int n = r0 + i;
        float* op = attn + ((size_t)(b*SEQ + n))*DIM + head*DH + c0;
        *(float4*)(op)   = make_float4(acc[i][0], acc[i][1], acc[i][2], acc[i][3]);
        *(float4*)(op+4) = make_float4(acc[i][4], acc[i][5], acc[i][6], acc[i][7]);
    }
}

// ---------------- launch ---------------------------------------------------
extern "C" void kernel_launch(void* const* d_in, const int* in_sizes, int n_in,
                              void* d_out, int out_size)
{
    const float* x    = (const float*)d_in[0];
    const float* ln1g = (const float*)d_in[1];
    const float* ln1b = (const float*)d_in[2];
    const float* wq   = (const float*)d_in[3];
    const float* wk   = (const float*)d_in[4];
    const float* wv   = (const float*)d_in[5];
    const float* wo   = (const float*)d_in[6];
    const float* bo   = (const float*)d_in[7];
    const float* ln2g = (const float*)d_in[8];
    const float* ln2b = (const float*)d_in[9];
    const float* wff1 = (const float*)d_in[10];
    const float* bff1 = (const float*)d_in[11];
    const float* wff2 = (const float*)d_in[12];
    const float* bff2 = (const float*)d_in[13];
    const float* wd   = (const float*)d_in[14];
    const float* bd   = (const float*)d_in[15];
    float* out = (float*)d_out;

    float *h,*q,*k,*v,*ctx,*attn,*x1,*x2,*ff,*part;
    cudaGetSymbolAddress((void**)&h,    g_h);
    cudaGetSymbolAddress((void**)&q,    g_q);
    cudaGetSymbolAddress((void**)&k,    g_k);
    cudaGetSymbolAddress((void**)&v,    g_v);
    cudaGetSymbolAddress((void**)&ctx,  g_ctx);
    cudaGetSymbolAddress((void**)&attn, g_attn);
    cudaGetSymbolAddress((void**)&x1,   g_x1);
    cudaGetSymbolAddress((void**)&x2,   g_x2);
    cudaGetSymbolAddress((void**)&ff,   g_ff);
    cudaGetSymbolAddress((void**)&part, g_part);

    // --- attention block ---
    ln_kernel<<<TOK, 256>>>(x, ln1g, ln1b, h);
    gemm_main<3><<<dim3(8, 128), 256>>>(h, wq, nullptr, nullptr, q, TOK, DIM, DIM);
    gemm_main<3><<<dim3(8, 128), 256>>>(h, wk, nullptr, nullptr, k, TOK, DIM, DIM);
    gemm_main<3><<<dim3(8, 128), 256>>>(h, wv, nullptr, nullptr, v, TOK, DIM, DIM);
    qsm_kernel<<<(NBH*SEQ)/8, 256>>>(q);                 // 65536 rows, 8 warps/block
    ksm_partial<<<dim3(KCH, NBH), 256>>>(k, part);
    ksm_norm   <<<dim3(KCH, NBH), 256>>>(k, part);
    ctx_gemm   <<<dim3(4, 4, NBH), 256>>>(k, v, ctx);
    attn_gemm  <<<dim3(2, 32, NBH), 256>>>(q, ctx, attn);
    gemm_main<1><<<dim3(8, 128), 256>>>(attn, wo, bo, x, x1, TOK, DIM, DIM);

    // --- FFN block ---
    ln_kernel<<<TOK, 256>>>(x1, ln2g, ln2b, h);
    gemm_main<2><<<dim3(32, 128), 256>>>(h, wff1, bff1, nullptr, ff, TOK, FFD, DIM);
    gemm_main<1><<<dim3(8, 128), 256>>>(ff, wff2, bff2, x1, x2, TOK, DIM, FFD);

    // --- trailing dense ---
    gemm_main<0><<<dim3(8, 128), 256>>>(x2, wd, bd, nullptr, out, TOK, DIM, DIM);
}

// round 4
// speedup vs baseline: 2.1169x; 2.1169x over previous
#include <cuda_runtime.h>
#include <math.h>
#include <stdint.h>

#define BATCH 4
#define SEQ   4096
#define DIM   1024
#define NH    4
#define DH    256
#define FFD   4096
#define TOK   (BATCH*SEQ)   /* 16384 */
#define NBH   (BATCH*NH)    /* 16 */
#define KCH   16
#define CHUNK (SEQ/KCH)     /* 256 */

/* mma GEMM tiling */
#define TM 128
#define TN 128
#define TK 32
#define APITCH 36
#define BPITCH 136
#define ABYTES (TM*APITCH*4)      /* 18432 */
#define BBYTES (TK*BPITCH*4)      /* 17408 */
#define SMEM2  (2*(ABYTES+BBYTES)) /* 71680 */

// ---------------- scratch ---------------------------------------------------
__device__ float g_h   [(size_t)TOK*DIM];
__device__ float g_q   [(size_t)NBH*SEQ*DH];
__device__ float g_k   [(size_t)NBH*SEQ*DH];
__device__ float g_v   [(size_t)NBH*SEQ*DH];
__device__ float g_ctx [(size_t)NBH*DH*DH];
__device__ float g_attn[(size_t)TOK*DIM];
__device__ float g_x1  [(size_t)TOK*DIM];
__device__ float g_x2  [(size_t)TOK*DIM];
__device__ float g_ff  [(size_t)TOK*FFD];
__device__ float g_part[NBH*KCH*2*DH];

__device__ __forceinline__ float gelu_tanh(float x) {
    float x3 = x*x*x;
    return 0.5f*x*(1.0f + tanhf(0.7978845608028654f*(x + 0.044715f*x3)));
}

__device__ __forceinline__ uint32_t smem_u32(const void* p) {
    uint32_t a;
    asm("{ .reg .u64 t; cvta.to.shared.u64 t, %1; cvt.u32.u64 %0, t; }" : "=r"(a) : "l"(p));
    return a;
}
__device__ __forceinline__ void cp16(uint32_t dst, const void* src) {
    asm volatile("cp.async.cg.shared.global [%0], [%1], 16;" :: "r"(dst), "l"(src));
}
__device__ __forceinline__ uint32_t f2tf32(float x) {
    uint32_t u;
    asm("cvt.rna.tf32.f32 %0, %1;" : "=r"(u) : "f"(x));
    return u;
}
__device__ __forceinline__ void mma_tf32(float* c, uint32_t a0, uint32_t a1, uint32_t a2,
                                         uint32_t a3, uint32_t b0, uint32_t b1) {
    asm volatile("mma.sync.aligned.m16n8k8.row.col.f32.tf32.tf32.f32 "
        "{%0,%1,%2,%3}, {%4,%5,%6,%7}, {%8,%9}, {%0,%1,%2,%3};"
        : "+f"(c[0]), "+f"(c[1]), "+f"(c[2]), "+f"(c[3])
        : "r"(a0), "r"(a1), "r"(a2), "r"(a3), "r"(b0), "r"(b1));
}

// ---------------- mma.sync tf32 GEMM, 128x128 tiles, fused epilogues --------
// MODE 0: C = acc + bias
// MODE 1: C = acc + bias + res
// MODE 2: C = gelu(acc + bias)
// MODE 3: C = acc scattered to [b,h,n,dh] (tile lies within one head: 128|256)
template<int MODE>
__global__ void __launch_bounds__(256, 1)
gemm_mma(const float* __restrict__ A, const float* __restrict__ W,
         const float* __restrict__ bias, const float* __restrict__ res,
         float* __restrict__ C, int Ncols, int K)
{
    extern __shared__ char dsm[];
    float* As[2] = { (float*)dsm,                (float*)(dsm + ABYTES) };
    float* Bs[2] = { (float*)(dsm + 2*ABYTES),   (float*)(dsm + 2*ABYTES + BBYTES) };
    const uint32_t aAs[2] = { smem_u32(As[0]), smem_u32(As[1]) };
    const uint32_t aBs[2] = { smem_u32(Bs[0]), smem_u32(Bs[1]) };

    const int tid  = threadIdx.x;
    const int lane = tid & 31;
    const int w    = tid >> 5;
    const int m0w  = (w >> 2) * 64;     /* warp M offset in tile */
    const int n0w  = (w & 3) * 32;      /* warp N offset in tile */
    const int row0 = blockIdx.y * TM;
    const int col0 = blockIdx.x * TN;
    const int NT   = K / TK;

    const int lr = lane >> 2;           /* 0..7  */
    const int lc = lane & 3;            /* 0..3  */

    auto fill = [&](int buf, int k0) {
        /* A: 128 rows x 32 cols -> 1024 float4 */
        #pragma unroll
        for (int j = 0; j < 4; j++) {
            int f  = tid + 256*j;
            int r  = f >> 3, c4 = f & 7;
            cp16(aAs[buf] + (uint32_t)(r*APITCH + c4*4)*4,
                 A + (size_t)(row0 + r)*K + k0 + c4*4);
        }
        /* B: 32 rows x 128 cols -> 1024 float4 */
        #pragma unroll
        for (int j = 0; j < 4; j++) {
            int f  = tid + 256*j;
            int kr = f >> 5, c4 = f & 31;
            cp16(aBs[buf] + (uint32_t)(kr*BPITCH + c4*4)*4,
                 W + (size_t)(k0 + kr)*Ncols + col0 + c4*4);
        }
        asm volatile("cp.async.commit_group;");
    };

    float acc[4][4][4];
    #pragma unroll
    for (int i = 0; i < 4; i++)
        #pragma unroll
        for (int j = 0; j < 4; j++)
            #pragma unroll
            for (int r = 0; r < 4; r++) acc[i][j][r] = 0.f;

    fill(0, 0);

    for (int t = 0; t < NT; t++) {
        if (t + 1 < NT) {
            fill((t + 1) & 1, (t + 1) * TK);
            asm volatile("cp.async.wait_group 1;");
        } else {
            asm volatile("cp.async.wait_group 0;");
        }
        __syncthreads();

        const float* Ab = As[t & 1];
        const float* Bb = Bs[t & 1];

        #pragma unroll
        for (int kk = 0; kk < 4; kk++) {
            const int kc = kk*8 + lc;
            uint32_t af[4][4];
            #pragma unroll
            for (int mf = 0; mf < 4; mf++) {
                const float* ap = Ab + (m0w + mf*16 + lr)*APITCH + kc;
                af[mf][0] = f2tf32(ap[0]);
                af[mf][1] = f2tf32(ap[8*APITCH]);
                af[mf][2] = f2tf32(ap[4]);
                af[mf][3] = f2tf32(ap[8*APITCH + 4]);
            }
            uint32_t bf[4][2];
            #pragma unroll
            for (int nf = 0; nf < 4; nf++) {
                const float* bp = Bb + kc*BPITCH + n0w + nf*8 + lr;
                bf[nf][0] = f2tf32(bp[0]);
                bf[nf][1] = f2tf32(bp[4*BPITCH]);
            }
            #pragma unroll
            for (int mf = 0; mf < 4; mf++)
                #pragma unroll
                for (int nf = 0; nf < 4; nf++)
                    mma_tf32(acc[mf][nf], af[mf][0], af[mf][1], af[mf][2], af[mf][3],
                             bf[nf][0], bf[nf][1]);
        }
        __syncthreads();
    }

    // ---- epilogue ----
    #pragma unroll
    for (int mf = 0; mf < 4; mf++) {
        #pragma unroll
        for (int half = 0; half < 2; half++) {
            const int grow = row0 + m0w + mf*16 + lr + half*8;
            #pragma unroll
            for (int nf = 0; nf < 4; nf++) {
                const int gcol = col0 + n0w + nf*8 + 2*lc;
                float v0 = acc[mf][nf][half*2 + 0];
                float v1 = acc[mf][nf][half*2 + 1];
                if (MODE == 3) {
                    const int head = gcol >> 8;
                    const int dh0  = gcol & 255;
                    const int b_   = grow >> 12;
                    const int n_   = grow & 4095;
                    float* op = C + ((size_t)((b_*NH + head)*SEQ + n_))*DH + dh0;
                    *(float2*)op = make_float2(v0, v1);
                } else {
                    v0 += bias[gcol];
                    v1 += bias[gcol + 1];
                    if (MODE == 2) { v0 = gelu_tanh(v0); v1 = gelu_tanh(v1); }
                    if (MODE == 1) {
                        const float2 rv = *(const float2*)(res + (size_t)grow*Ncols + gcol);
                        v0 += rv.x; v1 += rv.y;
                    }
                    *(float2*)(C + (size_t)grow*Ncols + gcol) = make_float2(v0, v1);
                }
            }
        }
    }
}

// ---------------- LayerNorm -------------------------------------------------
__global__ void ln_kernel(const float* __restrict__ x, const float* __restrict__ g,
                          const float* __restrict__ b, float* __restrict__ out)
{
    __shared__ float red[16];
    __shared__ float s_mu, s_rstd;
    const int row = blockIdx.x, t = threadIdx.x;
    const float4 v = ((const float4*)(x + (size_t)row*DIM))[t];
    float s  = v.x + v.y + v.z + v.w;
    float ss = fmaf(v.x,v.x, fmaf(v.y,v.y, fmaf(v.z,v.z, v.w*v.w)));
    #pragma unroll
    for (int o = 16; o > 0; o >>= 1) {
        s  += __shfl_xor_sync(0xffffffffu, s,  o);
        ss += __shfl_xor_sync(0xffffffffu, ss, o);
    }
    const int w = t >> 5, lane = t & 31;
    if (lane == 0) { red[w] = s; red[8+w] = ss; }
    __syncthreads();
    if (t == 0) {
        float S = 0.f, SS = 0.f;
        #pragma unroll
        for (int i = 0; i < 8; i++) { S += red[i]; SS += red[8+i]; }
        float mu  = S  * (1.0f/DIM);
        float var = SS * (1.0f/DIM) - mu*mu;
        s_mu = mu; s_rstd = rsqrtf(var + 1e-5f);
    }
    __syncthreads();
    const float mu = s_mu, r = s_rstd;
    const float4 gv = ((const float4*)g)[t];
    const float4 bv = ((const float4*)b)[t];
    float4 o;
    o.x = (v.x-mu)*r*gv.x + bv.x;
    o.y = (v.y-mu)*r*gv.y + bv.y;
    o.z = (v.z-mu)*r*gv.z + bv.z;
    o.w = (v.w-mu)*r*gv.w + bv.w;
    ((float4*)(out + (size_t)row*DIM))[t] = o;
}

// ---------------- q softmax over head dim -----------------------------------
__global__ void qsm_kernel(float* __restrict__ q)
{
    const int warp = (blockIdx.x * blockDim.x + threadIdx.x) >> 5;
    const int lane = threadIdx.x & 31;
    float* row = q + (size_t)warp * DH;
    float v[8];
    float m = -INFINITY;
    #pragma unroll
    for (int j = 0; j < 8; j++) { v[j] = row[j*32 + lane] * 0.25f; m = fmaxf(m, v[j]); }
    #pragma unroll
    for (int o = 16; o > 0; o >>= 1) m = fmaxf(m, __shfl_xor_sync(0xffffffffu, m, o));
    float s = 0.f;
    #pragma unroll
    for (int j = 0; j < 8; j++) { v[j] = expf(v[j] - m); s += v[j]; }
    #pragma unroll
    for (int o = 16; o > 0; o >>= 1) s += __shfl_xor_sync(0xffffffffu, s, o);
    const float inv = 1.0f / s;
    #pragma unroll
    for (int j = 0; j < 8; j++) row[j*32 + lane] = v[j] * inv;
}

// ---------------- k softmax over sequence dim (2-pass chunked) --------------
__global__ void ksm_partial(const float* __restrict__ k, float* __restrict__ part)
{
    const int bh = blockIdx.y, ch = blockIdx.x, t = threadIdx.x;
    const float* kp = k + ((size_t)bh*SEQ + (size_t)ch*CHUNK)*DH + t;
    float m = -INFINITY, s = 0.f;
    for (int i = 0; i < CHUNK; i++) {
        const float vv = kp[(size_t)i*DH] * 0.25f;
        const float nm = fmaxf(m, vv);
        s = s*expf(m - nm) + expf(vv - nm);
        m = nm;
    }
    float* pp = part + (size_t)((bh*KCH + ch)*2)*DH;
    pp[t] = m; pp[DH + t] = s;
}

__global__ void ksm_norm(float* __restrict__ k, const float* __restrict__ part)
{
    const int bh = blockIdx.y, ch = blockIdx.x, t = threadIdx.x;
    float M = -INFINITY;
    #pragma unroll
    for (int c = 0; c < KCH; c++)
        M = fmaxf(M, part[(size_t)((bh*KCH + c)*2)*DH + t]);
    float S = 0.f;
    #pragma unroll
    for (int c = 0; c < KCH; c++) {
        const float* pp = part + (size_t)((bh*KCH + c)*2)*DH;
        S += pp[DH + t] * expf(pp[t] - M);
    }
    const float inv = 1.0f / S;
    float* kp = k + ((size_t)bh*SEQ + (size_t)ch*CHUNK)*DH + t;
    for (int i = 0; i < CHUNK; i++) {
        const float vv = kp[(size_t)i*DH] * 0.25f;
        kp[(size_t)i*DH] = expf(vv - M) * inv;
    }
}

// ---------------- ctx = k^T @ v  (per bh: 256x4096^T x 4096x256) ------------
__global__ void __launch_bounds__(256)
ctx_gemm(const float* __restrict__ k, const float* __restrict__ v, float* __restrict__ ctx)
{
    __shared__ float As[16][64];
    __shared__ float Bs[16][64];
    const int bh = blockIdx.z;
    const int m0 = blockIdx.y * 64, e0 = blockIdx.x * 64;
    const int tid = threadIdx.x;
    const int tx = tid & 15, ty = tid >> 4;
    const int lr = tid >> 4;
    const int lc = (tid & 15) * 4;
    const float* kb = k + (size_t)bh*SEQ*DH;
    const float* vb = v + (size_t)bh*SEQ*DH;
    float acc[4][4] = {};

    for (int n0 = 0; n0 < SEQ; n0 += 16) {
        *(float4*)&As[lr][lc] = *(const float4*)(kb + (size_t)(n0+lr)*DH + m0 + lc);
        *(float4*)&Bs[lr][lc] = *(const float4*)(vb + (size_t)(n0+lr)*DH + e0 + lc);
        __syncthreads();
        #pragma unroll
        for (int kk = 0; kk < 16; kk++) {
            float4 a = *(const float4*)&As[kk][ty*4];
            float4 b = *(const float4*)&Bs[kk][tx*4];
            const float ar[4] = {a.x,a.y,a.z,a.w};
            const float br[4] = {b.x,b.y,b.z,b.w};
            #pragma unroll
            for (int i = 0; i < 4; i++)
                #pragma unroll
                for (int j = 0; j < 4; j++)
                    acc[i][j] = fmaf(ar[i], br[j], acc[i][j]);
        }
        __syncthreads();
    }
    float* cb = ctx + (size_t)bh*DH*DH;
    #pragma unroll
    for (int i = 0; i < 4; i++)
        *(float4*)(cb + (size_t)(m0 + ty*4 + i)*DH + e0 + tx*4) =
            make_float4(acc[i][0], acc[i][1], acc[i][2], acc[i][3]);
}

// ---------------- attn = q @ ctx, scatter to [b,n,d] ------------------------
__global__ void __launch_bounds__(256)
attn_gemm(const float* __restrict__ q, const float* __restrict__ ctx, float* __restrict__ attn)
{
    __shared__ float As[8][128];
    __shared__ float Bs[8][128];
    const int bh = blockIdx.z;
    const int b = bh >> 2, head = bh & 3;
    const float* A = q   + (size_t)bh*SEQ*DH;
    const float* W = ctx + (size_t)bh*DH*DH;
    const int tid = threadIdx.x;
    const int tx = tid & 15, ty = tid >> 4;
    const int row0 = blockIdx.y * 128, col0 = blockIdx.x * 128;
    const int a_row = tid >> 1, a_col = (tid & 1) * 4;
    const int b_row = tid >> 5, b_col = (tid & 31) * 4;
    const float* Ap = A + (size_t)(row0 + a_row)*DH + a_col;
    const float* Wp = W + (size_t)b_row*DH + col0 + b_col;
    float acc[8][8] = {};

    for (int k0 = 0; k0 < DH; k0 += 8) {
        float4 av = *(const float4*)Ap;
        float4 bv = *(const float4*)Wp;
        As[a_col+0][a_row] = av.x;
        As[a_col+1][a_row] = av.y;
        As[a_col+2][a_row] = av.z;
        As[a_col+3][a_row] = av.w;
        *(float4*)&Bs[b_row][b_col] = bv;
        __syncthreads();
        #pragma unroll
        for (int kk = 0; kk < 8; kk++) {
            float4 a0 = *(const float4*)&As[kk][ty*8];
            float4 a1 = *(const float4*)&As[kk][ty*8+4];
            float4 b0 = *(const float4*)&Bs[kk][tx*8];
            float4 b1 = *(const float4*)&Bs[kk][tx*8+4];
            float ar[8] = {a0.x,a0.y,a0.z,a0.w,a1.x,a1.y,a1.z,a1.w};
            float br[8] = {b0.x,b0.y,b0.z,b0.w,b1.x,b1.y,b1.z,b1.w};
            #pragma unroll
            for (int i = 0; i < 8; i++)
                #pragma unroll
                for (int j = 0; j < 8; j++)
                    acc[i][j] = fmaf(ar[i], br[j], acc[i][j]);
        }
        __syncthreads();
        Ap += 8;
        Wp += 8*DH;
    }

    const int r0 = row0 + ty*8;
    const int c0 = col0 + tx*8;
    #pragma unroll
    for (int i = 0; i < 8; i++) {
        const int n = r0 + i;
        float* op = attn + ((size_t)(b*SEQ + n))*DIM + head*DH + c0;
        *(float4*)(op)   = make_float4(acc[i][0], acc[i][1], acc[i][2], acc[i][3]);
        *(float4*)(op+4) = make_float4(acc[i][4], acc[i][5], acc[i][6], acc[i][7]);
    }
}

// ---------------- launch ----------------------------------------------------
extern "C" void kernel_launch(void* const* d_in, const int* in_sizes, int n_in,
                              void* d_out, int out_size)
{
    const float* x    = (const float*)d_in[0];
    const float* ln1g = (const float*)d_in[1];
    const float* ln1b = (const float*)d_in[2];
    const float* wq   = (const float*)d_in[3];
    const float* wk   = (const float*)d_in[4];
    const float* wv   = (const float*)d_in[5];
    const float* wo   = (const float*)d_in[6];
    const float* bo   = (const float*)d_in[7];
    const float* ln2g = (const float*)d_in[8];
    const float* ln2b = (const float*)d_in[9];
    const float* wff1 = (const float*)d_in[10];
    const float* bff1 = (const float*)d_in[11];
    const float* wff2 = (const float*)d_in[12];
    const float* bff2 = (const float*)d_in[13];
    const float* wd   = (const float*)d_in[14];
    const float* bd   = (const float*)d_in[15];
    float* out = (float*)d_out;

    float *h,*q,*k,*v,*ctx,*attn,*x1,*x2,*ff,*part;
    cudaGetSymbolAddress((void**)&h,    g_h);
    cudaGetSymbolAddress((void**)&q,    g_q);
    cudaGetSymbolAddress((void**)&k,    g_k);
    cudaGetSymbolAddress((void**)&v,    g_v);
    cudaGetSymbolAddress((void**)&ctx,  g_ctx);
    cudaGetSymbolAddress((void**)&attn, g_attn);
    cudaGetSymbolAddress((void**)&x1,   g_x1);
    cudaGetSymbolAddress((void**)&x2,   g_x2);
    cudaGetSymbolAddress((void**)&ff,   g_ff);
    cudaGetSymbolAddress((void**)&part, g_part);

    cudaFuncSetAttribute(gemm_mma<0>, cudaFuncAttributeMaxDynamicSharedMemorySize, SMEM2);
    cudaFuncSetAttribute(gemm_mma<1>, cudaFuncAttributeMaxDynamicSharedMemorySize, SMEM2);
    cudaFuncSetAttribute(gemm_mma<2>, cudaFuncAttributeMaxDynamicSharedMemorySize, SMEM2);
    cudaFuncSetAttribute(gemm_mma<3>, cudaFuncAttributeMaxDynamicSharedMemorySize, SMEM2);

    // --- attention block ---
    ln_kernel<<<TOK, 256>>>(x, ln1g, ln1b, h);
    gemm_mma<3><<<dim3(8, 128), 256, SMEM2>>>(h, wq, nullptr, nullptr, q, DIM, DIM);
    gemm_mma<3><<<dim3(8, 128), 256, SMEM2>>>(h, wk, nullptr, nullptr, k, DIM, DIM);
    gemm_mma<3><<<dim3(8, 128), 256, SMEM2>>>(h, wv, nullptr, nullptr, v, DIM, DIM);
    qsm_kernel<<<(NBH*SEQ)/8, 256>>>(q);
    ksm_partial<<<dim3(KCH, NBH), 256>>>(k, part);
    ksm_norm   <<<dim3(KCH, NBH), 256>>>(k, part);
    ctx_gemm   <<<dim3(4, 4, NBH), 256>>>(k, v, ctx);
    attn_gemm  <<<dim3(2, 32, NBH), 256>>>(q, ctx, attn);
    gemm_mma<1><<<dim3(8, 128), 256, SMEM2>>>(attn, wo, bo, x, x1, DIM, DIM);

    // --- FFN block ---
    ln_kernel<<<TOK, 256>>>(x1, ln2g, ln2b, h);
    gemm_mma<2><<<dim3(32, 128), 256, SMEM2>>>(h, wff1, bff1, nullptr, ff, FFD, DIM);
    gemm_mma<1><<<dim3(8, 128), 256, SMEM2>>>(ff, wff2, bff2, x1, x2, DIM, FFD);

    // --- trailing dense ---
    gemm_mma<0><<<dim3(8, 128), 256, SMEM2>>>(x2, wd, bd, nullptr, out, DIM, DIM);
}